// round 6
// baseline (speedup 1.0000x reference)
#include <cuda_runtime.h>

// T=4 LIF over repeated input.
// in:  (B=32, L=720, C=862) f32  ->  out: (T=4, B=32, C=862, L=720) f32 spikes
// Per element: v=0; 4x { v=(v+x)/2; s=(v>=1); if(s) v=0; }
//
// R6: split read-stream and write-stream to kill DRAM read/write turnaround.
//  K1: read input, transpose, pack 4 spike bits -> 1 byte/elem into L2-resident
//      scratch (19.9MB). 79.4MB R + 19.9MB W.
//  K2: expand bytes (L2 hits) -> 317.8MB nearly-pure write stream.

#define L_DIM 720
#define C_DIM 862
#define B_DIM 32
#define T_STEPS 4
#define TILE 32
#define L4_DIM (L_DIM / 4)                  // 180
#define N_K2 (B_DIM * C_DIM * L4_DIM)       // 4,965,120 (divisible by 256)

__device__ unsigned char g_spk[(size_t)B_DIM * C_DIM * L_DIM];   // 19.86 MB scratch

// ---------------- K1: LIF + transpose + bit-pack ----------------
__global__ __launch_bounds__(256, 8)
void lif_pack_kernel(const float* __restrict__ in) {
    __shared__ float tile[TILE][TILE + 1];

    const int b     = blockIdx.z;
    const int lBase = blockIdx.y * TILE;
    const int cBase = blockIdx.x * TILE;
    const int tx = threadIdx.x & 31;
    const int ty = threadIdx.x >> 5;

    const float* inb = in + (size_t)b * ((size_t)L_DIM * C_DIM);
    const int c_in = cBase + tx;
    if (c_in < C_DIM) {
#pragma unroll
        for (int k = 0; k < 4; k++) {
            int l = lBase + ty + k * 8;
            if (l < L_DIM)
                tile[ty + k * 8][tx] = __ldcs(inb + (size_t)l * C_DIM + c_in);
        }
    }
    __syncthreads();

    const int tid     = threadIdx.x;
    const int c_local = tid >> 3;
    const int l4      = tid & 7;
    const int c = cBase + c_local;
    const int l = lBase + l4 * 4;
    if (c >= C_DIM || l >= L_DIM) return;

    unsigned char by[4];
#pragma unroll
    for (int j = 0; j < 4; j++) {
        float x = tile[l4 * 4 + j][c_local];
        float v = 0.0f;
        unsigned int bits = 0;
#pragma unroll
        for (int t = 0; t < T_STEPS; t++) {
            v = (v + x) * 0.5f;
            bool fire = (v >= 1.0f);
            bits |= ((unsigned int)fire) << t;
            v = fire ? 0.0f : v;
        }
        by[j] = (unsigned char)bits;
    }
    uchar4 s4 = make_uchar4(by[0], by[1], by[2], by[3]);
    // default store: keep resident in L2 for K2
    *reinterpret_cast<uchar4*>(g_spk + ((size_t)b * C_DIM + c) * L_DIM + l) = s4;
}

// ---------------- K2: expand bits -> 4 f32 planes (pure write stream) ----------------
__global__ __launch_bounds__(256)
void spike_expand_kernel(float* __restrict__ out) {
    const int idx = blockIdx.x * 256 + threadIdx.x;
    if (idx >= N_K2) return;

    const int b   = idx / (C_DIM * L4_DIM);
    const int rem = idx - b * (C_DIM * L4_DIM);
    const int c   = rem / L4_DIM;
    const int l4  = rem - c * L4_DIM;

    const uchar4 s = *reinterpret_cast<const uchar4*>(
        g_spk + ((size_t)b * C_DIM + c) * L_DIM + l4 * 4);   // L2 hit (warm from K1)

    const size_t plane = (size_t)B_DIM * C_DIM * L_DIM;
    float* ob = out + (size_t)b * ((size_t)C_DIM * L_DIM) + (size_t)c * L_DIM + l4 * 4;

#pragma unroll
    for (int t = 0; t < T_STEPS; t++) {
        float4 v4 = make_float4((float)((s.x >> t) & 1),
                                (float)((s.y >> t) & 1),
                                (float)((s.z >> t) & 1),
                                (float)((s.w >> t) & 1));
        __stcs(reinterpret_cast<float4*>(ob + t * plane), v4);
    }
}

extern "C" void kernel_launch(void* const* d_in, const int* in_sizes, int n_in,
                              void* d_out, int out_size) {
    const float* in = (const float*)d_in[0];
    float* out = (float*)d_out;

    dim3 g1((C_DIM + TILE - 1) / TILE,   // 27
            (L_DIM + TILE - 1) / TILE,   // 23
            B_DIM);                      // 32
    lif_pack_kernel<<<g1, 256>>>(in);

    spike_expand_kernel<<<N_K2 / 256, 256>>>(out);   // 19395 blocks
}

// round 7
// speedup vs baseline: 1.2726x; 1.2726x over previous
#include <cuda_runtime.h>

// T=4 LIF over repeated input.
// in:  (B=32, L=720, C=862) f32  ->  out: (T=4, B=32, C=862, L=720) f32 spikes
// Per element: v=0; 4x { v=(v+x)/2; s=(v>=1); if(s) v=0; }
// HBM-bound: 79.4MB read + 317.8MB write = 397.2MB; achieved ceiling ~6.45TB/s
// (confirmed R6: pure-write stream hits the same 6.4TB/s as this mixed stream).
//
// R7 = R3 (best: 32x32 tile, padded smem, float4 full-line stores, __stcs)
// with grid swapped so consecutive blocks are adjacent in L: concurrent blocks
// write contiguous runs of the same output rows / read consecutive input rows.

#define L_DIM 720
#define C_DIM 862
#define B_DIM 32
#define T_STEPS 4
#define TILE 32

__global__ __launch_bounds__(256, 8)
void lif_transpose_kernel(const float* __restrict__ in, float* __restrict__ out) {
    __shared__ float tile[TILE][TILE + 1];

    const int b     = blockIdx.z;
    const int lBase = blockIdx.x * TILE;   // fast-varying block dim walks L
    const int cBase = blockIdx.y * TILE;
    const int tx = threadIdx.x;   // 0..31
    const int ty = threadIdx.y;   // 0..7

    // ---- load phase: coalesced along C (input-contiguous) ----
    const float* inb = in + (size_t)b * ((size_t)L_DIM * C_DIM);
    const int c_in = cBase + tx;
    if (c_in < C_DIM) {
#pragma unroll
        for (int k = 0; k < 4; k++) {
            int l = lBase + ty + k * 8;
            if (l < L_DIM)
                tile[ty + k * 8][tx] = inb[(size_t)l * C_DIM + c_in];
        }
    }
    __syncthreads();

    // ---- write phase: each thread owns (1 c, 4 consecutive l) -> float4 along L ----
    const int tid     = ty * 32 + tx;
    const int c_local = tid >> 3;      // 0..31
    const int l4      = tid & 7;       // 0..7
    const int c = cBase + c_local;
    const int l = lBase + l4 * 4;
    // L_DIM % 4 == 0, lBase % 32 == 0 -> each float4 fully valid or fully OOB.
    if (c >= C_DIM || l >= L_DIM) return;

    float sv[T_STEPS][4];
#pragma unroll
    for (int j = 0; j < 4; j++) {
        float x = tile[l4 * 4 + j][c_local];
        float v = 0.0f;
#pragma unroll
        for (int t = 0; t < T_STEPS; t++) {
            v = (v + x) * 0.5f;
            bool fire = (v >= 1.0f);
            sv[t][j] = fire ? 1.0f : 0.0f;
            v = fire ? 0.0f : v;
        }
    }

    const size_t plane = (size_t)B_DIM * C_DIM * L_DIM;
    float* obase = out + (size_t)b * ((size_t)C_DIM * L_DIM) + (size_t)c * L_DIM + l;
#pragma unroll
    for (int t = 0; t < T_STEPS; t++) {
        float4 v4 = make_float4(sv[t][0], sv[t][1], sv[t][2], sv[t][3]);
        __stcs(reinterpret_cast<float4*>(obase + t * plane), v4);
    }
}

extern "C" void kernel_launch(void* const* d_in, const int* in_sizes, int n_in,
                              void* d_out, int out_size) {
    const float* in = (const float*)d_in[0];
    float* out = (float*)d_out;
    dim3 block(32, 8);
    dim3 grid((L_DIM + TILE - 1) / TILE,   // 23  (L fast)
              (C_DIM + TILE - 1) / TILE,   // 27
              B_DIM);                      // 32
    lif_transpose_kernel<<<grid, block>>>(in, out);
}

// round 8
// speedup vs baseline: 1.2790x; 1.0050x over previous
#include <cuda_runtime.h>

// T=4 LIF over repeated input.
// in:  (B=32, L=720, C=862) f32  ->  out: (T=4, B=32, C=862, L=720) f32 spikes
// Per element: v=0; 4x { v=(v+x)/2; s=(v>=1); if(s) v=0; }
//
// FINAL (R8 = R3 + __ldcs): HBM-bound at the measured achieved ceiling.
// 397.2MB mandatory traffic / 6.45TB/s achieved ceiling = 61.6us floor;
// this kernel measures 61.3us (ncu). Verified across rounds: tile sizes
// 64x64/128x32 regress, persistent-pipeline regresses, stream-splitting
// regresses (adds traffic), block-order is LTS-hash-neutral, cache hints
// neutral. Pure-write streams hit the same 6.4TB/s => no mix-related
// headroom exists.

#define L_DIM 720
#define C_DIM 862
#define B_DIM 32
#define T_STEPS 4
#define TILE 32

__global__ __launch_bounds__(256, 8)
void lif_transpose_kernel(const float* __restrict__ in, float* __restrict__ out) {
    __shared__ float tile[TILE][TILE + 1];

    const int b     = blockIdx.z;
    const int lBase = blockIdx.y * TILE;
    const int cBase = blockIdx.x * TILE;
    const int tx = threadIdx.x;   // 0..31
    const int ty = threadIdx.y;   // 0..7

    // ---- load phase: coalesced along C (input-contiguous), streaming reads ----
    const float* inb = in + (size_t)b * ((size_t)L_DIM * C_DIM);
    const int c_in = cBase + tx;
    if (c_in < C_DIM) {
#pragma unroll
        for (int k = 0; k < 4; k++) {
            int l = lBase + ty + k * 8;
            if (l < L_DIM)
                tile[ty + k * 8][tx] = __ldcs(inb + (size_t)l * C_DIM + c_in);
        }
    }
    __syncthreads();

    // ---- write phase: each thread owns (1 c, 4 consecutive l) -> float4 along L.
    //      Warp covers 4 c-rows x 128B: every 128B output line written whole. ----
    const int tid     = ty * 32 + tx;
    const int c_local = tid >> 3;      // 0..31
    const int l4      = tid & 7;       // 0..7
    const int c = cBase + c_local;
    const int l = lBase + l4 * 4;
    // L_DIM % 4 == 0, lBase % 32 == 0 -> each float4 fully valid or fully OOB.
    if (c >= C_DIM || l >= L_DIM) return;

    float sv[T_STEPS][4];
#pragma unroll
    for (int j = 0; j < 4; j++) {
        float x = tile[l4 * 4 + j][c_local];
        float v = 0.0f;
#pragma unroll
        for (int t = 0; t < T_STEPS; t++) {
            v = (v + x) * 0.5f;
            bool fire = (v >= 1.0f);
            sv[t][j] = fire ? 1.0f : 0.0f;
            v = fire ? 0.0f : v;
        }
    }

    const size_t plane = (size_t)B_DIM * C_DIM * L_DIM;
    float* obase = out + (size_t)b * ((size_t)C_DIM * L_DIM) + (size_t)c * L_DIM + l;
#pragma unroll
    for (int t = 0; t < T_STEPS; t++) {
        float4 v4 = make_float4(sv[t][0], sv[t][1], sv[t][2], sv[t][3]);
        __stcs(reinterpret_cast<float4*>(obase + t * plane), v4);
    }
}

extern "C" void kernel_launch(void* const* d_in, const int* in_sizes, int n_in,
                              void* d_out, int out_size) {
    const float* in = (const float*)d_in[0];
    float* out = (float*)d_out;
    dim3 block(32, 8);
    dim3 grid((C_DIM + TILE - 1) / TILE,   // 27
              (L_DIM + TILE - 1) / TILE,   // 23
              B_DIM);                      // 32
    lif_transpose_kernel<<<grid, block>>>(in, out);
}

// round 9
// speedup vs baseline: 1.2810x; 1.0015x over previous
#include <cuda_runtime.h>

// T=4 LIF over repeated input.
// in:  (B=32, L=720, C=862) f32  ->  out: (T=4, B=32, C=862, L=720) f32 spikes
// Per element: v=0; 4x { v=(v+x)/2; s=(v>=1); if(s) v=0; }
//
// FINAL — at the HBM roofline. 397.2MB mandatory traffic / 6.45TB/s measured
// achieved ceiling = 61.6us floor; this kernel's ncu time is 61.2us.
// Converged evidence across 8 rounds:
//   - ceiling is mix-independent (pure-write stream also hits 6.4TB/s)
//   - 32x32 tile optimal (64x64 / 128x32 / persistent pipeline all regress)
//   - traffic splitting regresses (adds bytes), block order LTS-hash-neutral
//   - cache hints are noise; __stcs kept (best measured sample)
// Access pattern: loads fully coalesced along C; every 128B output line is
// written whole by one warp (float4 per thread, 4 c-rows per warp, 4 planes).

#define L_DIM 720
#define C_DIM 862
#define B_DIM 32
#define T_STEPS 4
#define TILE 32

__global__ __launch_bounds__(256, 8)
void lif_transpose_kernel(const float* __restrict__ in, float* __restrict__ out) {
    __shared__ float tile[TILE][TILE + 1];

    const int b     = blockIdx.z;
    const int lBase = blockIdx.y * TILE;
    const int cBase = blockIdx.x * TILE;
    const int tx = threadIdx.x;   // 0..31
    const int ty = threadIdx.y;   // 0..7

    // ---- load phase: coalesced along C (input-contiguous) ----
    const float* inb = in + (size_t)b * ((size_t)L_DIM * C_DIM);
    const int c_in = cBase + tx;
    if (c_in < C_DIM) {
#pragma unroll
        for (int k = 0; k < 4; k++) {
            int l = lBase + ty + k * 8;
            if (l < L_DIM)
                tile[ty + k * 8][tx] = inb[(size_t)l * C_DIM + c_in];
        }
    }
    __syncthreads();

    // ---- write phase: each thread owns (1 c, 4 consecutive l) -> float4 along L ----
    const int tid     = ty * 32 + tx;
    const int c_local = tid >> 3;      // 0..31
    const int l4      = tid & 7;       // 0..7
    const int c = cBase + c_local;
    const int l = lBase + l4 * 4;
    // L_DIM % 4 == 0, lBase % 32 == 0 -> each float4 fully valid or fully OOB.
    if (c >= C_DIM || l >= L_DIM) return;

    float sv[T_STEPS][4];
#pragma unroll
    for (int j = 0; j < 4; j++) {
        float x = tile[l4 * 4 + j][c_local];
        float v = 0.0f;
#pragma unroll
        for (int t = 0; t < T_STEPS; t++) {
            v = (v + x) * 0.5f;
            bool fire = (v >= 1.0f);
            sv[t][j] = fire ? 1.0f : 0.0f;
            v = fire ? 0.0f : v;
        }
    }

    const size_t plane = (size_t)B_DIM * C_DIM * L_DIM;
    float* obase = out + (size_t)b * ((size_t)C_DIM * L_DIM) + (size_t)c * L_DIM + l;
#pragma unroll
    for (int t = 0; t < T_STEPS; t++) {
        float4 v4 = make_float4(sv[t][0], sv[t][1], sv[t][2], sv[t][3]);
        __stcs(reinterpret_cast<float4*>(obase + t * plane), v4);
    }
}

extern "C" void kernel_launch(void* const* d_in, const int* in_sizes, int n_in,
                              void* d_out, int out_size) {
    const float* in = (const float*)d_in[0];
    float* out = (float*)d_out;
    dim3 block(32, 8);
    dim3 grid((C_DIM + TILE - 1) / TILE,   // 27
              (L_DIM + TILE - 1) / TILE,   // 23
              B_DIM);                      // 32
    lif_transpose_kernel<<<grid, block>>>(in, out);
}